// round 1
// baseline (speedup 1.0000x reference)
#include <cuda_runtime.h>
#include <math.h>

#define NMAX   50000
#define KDIM   128
#define COUT   40
#define BN_EPS 1e-5f

// ---------------- scratch (static device globals; no allocation) ----------------
__device__ float g_buf1[NMAX * KDIM];
__device__ float g_buf2[NMAX * KDIM];
__device__ float g_dinv[NMAX];
__device__ int   g_deg [NMAX];
__device__ float g_Wq  [KDIM * KDIM];
__device__ float g_stats[2 * KDIM];   // sums, sumsq
__device__ float g_sc   [2 * KDIM];   // scale, shift

// ---------------- degree / norm ----------------
__global__ void k_init_deg(int* deg, int n) {
    int i = blockIdx.x * blockDim.x + threadIdx.x;
    if (i < n) deg[i] = 1;  // self loop
}

__global__ void k_count_deg(const int* __restrict__ dst, int* deg, int E) {
    int e = blockIdx.x * blockDim.x + threadIdx.x;
    if (e < E) atomicAdd(&deg[dst[e]], 1);
}

__global__ void k_dinv(const int* __restrict__ deg, float* dinv, int n) {
    int i = blockIdx.x * blockDim.x + threadIdx.x;
    if (i < n) dinv[i] = rsqrtf((float)deg[i]);
}

// ---------------- weight fake-quant (symmetric 4-bit) ----------------
__global__ void k_quant_w(const float* __restrict__ W, const float* __restrict__ a,
                          float* __restrict__ Wq, int n) {
    int i = blockIdx.x * blockDim.x + threadIdx.x;
    if (i >= n) return;
    float s = a[0];
    float v = fminf(fmaxf(W[i] / s, -8.0f), 7.0f);
    Wq[i] = rintf(v) * s;
}

// ---------------- GEMM: warp per row, K=128, NC in {128,40} ----------------
__global__ void k_gemm(const float* __restrict__ X, const float* __restrict__ W,
                       const float* __restrict__ B, float* __restrict__ out,
                       int N, int NC) {
    int warp = (blockIdx.x * blockDim.x + threadIdx.x) >> 5;
    int lane = threadIdx.x & 31;
    if (warp >= N) return;
    const float* xr = X + (size_t)warp * KDIM;
    float xv0 = xr[lane], xv1 = xr[lane + 32], xv2 = xr[lane + 64], xv3 = xr[lane + 96];
    bool active = (lane * 4) < NC;
    int col = active ? lane * 4 : 0;
    float ax = 0.f, ay = 0.f, az = 0.f, aw = 0.f;
#pragma unroll
    for (int k = 0; k < KDIM; k++) {
        float src = (k < 32) ? xv0 : (k < 64) ? xv1 : (k < 96) ? xv2 : xv3;
        float xk = __shfl_sync(0xffffffffu, src, k & 31);
        float4 w = *(const float4*)(W + (size_t)k * NC + col);
        ax += xk * w.x; ay += xk * w.y; az += xk * w.z; aw += xk * w.w;
    }
    if (active) {
        float4 bb = *(const float4*)(B + col);
        float* o = out + (size_t)warp * NC + col;
        o[0] = ax + bb.x; o[1] = ay + bb.y; o[2] = az + bb.z; o[3] = aw + bb.w;
    }
}

// ---------------- aggregation ----------------
// self loop: out[i] = dinv[i]^2 * in[i]
__global__ void k_agg_init(const float* __restrict__ in, const float* __restrict__ dinv,
                           float* __restrict__ out, int n, int C) {
    int idx = blockIdx.x * blockDim.x + threadIdx.x;
    if (idx >= n * C) return;
    int row = idx / C;
    float d = dinv[row];
    out[idx] = d * d * in[idx];
}

__device__ __forceinline__ void red_add_v4(float* p, float x, float y, float z, float w) {
    asm volatile("red.global.add.v4.f32 [%0], {%1,%2,%3,%4};"
                 :: "l"(__cvta_generic_to_global(p)), "f"(x), "f"(y), "f"(z), "f"(w)
                 : "memory");
}

// warp per edge, C=128 (32 lanes x float4)
__global__ void k_agg_edges128(const int* __restrict__ src, const int* __restrict__ dst,
                               const float* __restrict__ dinv,
                               const float* __restrict__ in, float* __restrict__ out, int E) {
    int e = (blockIdx.x * blockDim.x + threadIdx.x) >> 5;
    int lane = threadIdx.x & 31;
    if (e >= E) return;
    int s = src[e], d = dst[e];
    float nrm = dinv[s] * dinv[d];
    float4 v = *((const float4*)(in + (size_t)s * KDIM) + lane);
    red_add_v4(out + (size_t)d * KDIM + lane * 4,
               v.x * nrm, v.y * nrm, v.z * nrm, v.w * nrm);
}

// thread per (edge, quad) for C=40 (10 float4 per edge)
__global__ void k_agg_edges40(const int* __restrict__ src, const int* __restrict__ dst,
                              const float* __restrict__ dinv,
                              const float* __restrict__ in, float* __restrict__ out, int E) {
    int t = blockIdx.x * blockDim.x + threadIdx.x;
    if (t >= E * 10) return;
    int e = t / 10;
    int q = t - e * 10;
    int s = src[e], d = dst[e];
    float nrm = dinv[s] * dinv[d];
    float4 v = *(const float4*)(in + (size_t)s * COUT + q * 4);
    red_add_v4(out + (size_t)d * COUT + q * 4,
               v.x * nrm, v.y * nrm, v.z * nrm, v.w * nrm);
}

// ---------------- batch norm ----------------
__global__ void k_zero_stats(float* stats) {
    int i = threadIdx.x;
    if (i < 2 * KDIM) stats[i] = 0.f;
}

__global__ void k_bn_stats(const float* __restrict__ in, float* stats, int n) {
    int c = threadIdx.x;  // blockDim = 128
    float s = 0.f, sq = 0.f;
    for (int r = blockIdx.x; r < n; r += gridDim.x) {
        float v = in[(size_t)r * KDIM + c];
        s += v; sq += v * v;
    }
    atomicAdd(&stats[c], s);
    atomicAdd(&stats[KDIM + c], sq);
}

__global__ void k_bn_finalize(const float* __restrict__ stats,
                              const float* __restrict__ g, const float* __restrict__ b,
                              float* sc, int n) {
    int c = threadIdx.x;  // blockDim = 128
    float inv_n = 1.0f / (float)n;
    float mean = stats[c] * inv_n;
    float var  = stats[KDIM + c] * inv_n - mean * mean;
    float scale = g[c] * rsqrtf(var + BN_EPS);
    sc[c] = scale;
    sc[KDIM + c] = b[c] - mean * scale;
}

// fused BN apply + ReLU + positive 4-bit fake quant (per-node scale)
__global__ void k_bn_relu_fq(const float* __restrict__ in, const float* __restrict__ sc,
                             const float* __restrict__ gq, float* __restrict__ out, int n) {
    int idx = blockIdx.x * blockDim.x + threadIdx.x;
    if (idx >= n * KDIM) return;
    int c = idx & (KDIM - 1);
    int row = idx >> 7;
    float v = in[idx] * sc[c] + sc[KDIM + c];
    v = fmaxf(v, 0.f);
    float g = gq[row];
    float u = fminf(fmaxf(v / g, 0.f), 15.0f);
    out[idx] = rintf(u) * g;
}

// ---------------- log softmax over 40 ----------------
__global__ void k_logsoftmax(const float* __restrict__ in, float* __restrict__ out, int n) {
    int row = (blockIdx.x * blockDim.x + threadIdx.x) >> 5;
    int lane = threadIdx.x & 31;
    if (row >= n) return;
    const float* r = in + (size_t)row * COUT;
    float a = r[lane];
    float b = (lane < 8) ? r[32 + lane] : -INFINITY;
    float m = fmaxf(a, b);
#pragma unroll
    for (int o = 16; o > 0; o >>= 1) m = fmaxf(m, __shfl_xor_sync(0xffffffffu, m, o));
    float s = expf(a - m) + ((lane < 8) ? expf(b - m) : 0.f);
#pragma unroll
    for (int o = 16; o > 0; o >>= 1) s += __shfl_xor_sync(0xffffffffu, s, o);
    float ls = logf(s);
    float* w = out + (size_t)row * COUT;
    w[lane] = a - m - ls;
    if (lane < 8) w[32 + lane] = b - m - ls;
}

// ---------------- host ----------------
static inline int cdiv(int a, int b) { return (a + b - 1) / b; }

extern "C" void kernel_launch(void* const* d_in, const int* in_sizes, int n_in,
                              void* d_out, int out_size) {
    const float* x    = (const float*)d_in[0];
    const int*   ei   = (const int*)d_in[1];
    const float* W1   = (const float*)d_in[2];
    const float* b1   = (const float*)d_in[3];
    const float* a1   = (const float*)d_in[4];
    const float* W2   = (const float*)d_in[5];
    const float* b2   = (const float*)d_in[6];
    const float* a2   = (const float*)d_in[7];
    const float* g2   = (const float*)d_in[8];
    const float* W3   = (const float*)d_in[9];
    const float* b3   = (const float*)d_in[10];
    const float* a3   = (const float*)d_in[11];
    const float* g3   = (const float*)d_in[12];
    const float* bn1g = (const float*)d_in[13];
    const float* bn1b = (const float*)d_in[14];
    const float* bn2g = (const float*)d_in[15];
    const float* bn2b = (const float*)d_in[16];

    const int N = in_sizes[0] / KDIM;
    const int E = in_sizes[1] / 2;
    const int* src = ei;
    const int* dst = ei + E;

    float *buf1, *buf2, *dinv, *Wq, *stats, *sc;
    int   *deg;
    cudaGetSymbolAddress((void**)&buf1,  g_buf1);
    cudaGetSymbolAddress((void**)&buf2,  g_buf2);
    cudaGetSymbolAddress((void**)&dinv,  g_dinv);
    cudaGetSymbolAddress((void**)&deg,   g_deg);
    cudaGetSymbolAddress((void**)&Wq,    g_Wq);
    cudaGetSymbolAddress((void**)&stats, g_stats);
    cudaGetSymbolAddress((void**)&sc,    g_sc);

    const int TB = 256;

    // degree / normalization (depends only on edges)
    k_init_deg<<<cdiv(N, TB), TB>>>(deg, N);
    k_count_deg<<<cdiv(E, TB), TB>>>(dst, deg, E);
    k_dinv<<<cdiv(N, TB), TB>>>(deg, dinv, N);

    // ---- layer 1 ----
    k_quant_w<<<cdiv(KDIM * KDIM, TB), TB>>>(W1, a1, Wq, KDIM * KDIM);
    k_gemm<<<cdiv(N * 32, TB), TB>>>(x, Wq, b1, buf1, N, KDIM);
    k_agg_init<<<cdiv(N * KDIM, TB), TB>>>(buf1, dinv, buf2, N, KDIM);
    k_agg_edges128<<<cdiv(E * 32, TB), TB>>>(src, dst, dinv, buf1, buf2, E);
    k_zero_stats<<<1, 256>>>(stats);
    k_bn_stats<<<512, 128>>>(buf2, stats, N);
    k_bn_finalize<<<1, 128>>>(stats, bn1g, bn1b, sc, N);
    k_bn_relu_fq<<<cdiv(N * KDIM, TB), TB>>>(buf2, sc, g2, buf1, N);

    // ---- layer 2 ----
    k_quant_w<<<cdiv(KDIM * KDIM, TB), TB>>>(W2, a2, Wq, KDIM * KDIM);
    k_gemm<<<cdiv(N * 32, TB), TB>>>(buf1, Wq, b2, buf2, N, KDIM);
    k_agg_init<<<cdiv(N * KDIM, TB), TB>>>(buf2, dinv, buf1, N, KDIM);
    k_agg_edges128<<<cdiv(E * 32, TB), TB>>>(src, dst, dinv, buf2, buf1, E);
    k_zero_stats<<<1, 256>>>(stats);
    k_bn_stats<<<512, 128>>>(buf1, stats, N);
    k_bn_finalize<<<1, 128>>>(stats, bn2g, bn2b, sc, N);
    k_bn_relu_fq<<<cdiv(N * KDIM, TB), TB>>>(buf1, sc, g3, buf2, N);

    // ---- layer 3 (output, C=40) ----
    k_quant_w<<<cdiv(KDIM * COUT, TB), TB>>>(W3, a3, Wq, KDIM * COUT);
    k_gemm<<<cdiv(N * 32, TB), TB>>>(buf2, Wq, b3, buf1, N, COUT);
    k_agg_init<<<cdiv(N * COUT, TB), TB>>>(buf1, dinv, buf2, N, COUT);
    k_agg_edges40<<<cdiv(E * 10, TB), TB>>>(src, dst, dinv, buf1, buf2, E);

    k_logsoftmax<<<cdiv(N * 32, TB), TB>>>(buf2, (float*)d_out, N);
}

// round 2
// speedup vs baseline: 1.1903x; 1.1903x over previous
#include <cuda_runtime.h>
#include <math.h>

#define NMAX   50000
#define EMAX   800000
#define KDIM   128
#define COUT   40
#define BN_EPS 1e-5f

// ---------------- scratch (static device globals; no allocation) ----------------
__device__ float g_buf1[NMAX * KDIM];
__device__ float g_buf2[NMAX * KDIM];
__device__ float g_dinv[NMAX];
__device__ int   g_deg [NMAX];
__device__ int   g_rowptr[NMAX + 1];
__device__ int   g_cursor[NMAX];
__device__ int   g_col [EMAX];
__device__ float g_norm[EMAX];
__device__ float g_Wq  [KDIM * KDIM];
__device__ float g_stats[2 * KDIM];   // sums, sumsq
__device__ float g_sc   [2 * KDIM];   // scale, shift

// ---------------- degree / norm ----------------
__global__ void k_init_deg(int* deg, int n) {
    int i = blockIdx.x * blockDim.x + threadIdx.x;
    if (i < n) deg[i] = 1;  // self loop
}

__global__ void k_count_deg(const int* __restrict__ dst, int* deg, int E) {
    int e = blockIdx.x * blockDim.x + threadIdx.x;
    if (e < E) atomicAdd(&deg[dst[e]], 1);
}

__global__ void k_dinv(const int* __restrict__ deg, float* dinv, int n) {
    int i = blockIdx.x * blockDim.x + threadIdx.x;
    if (i < n) dinv[i] = rsqrtf((float)deg[i]);
}

// ---------------- CSR build: exclusive scan of (deg-1) in one block ----------------
__global__ void k_scan_build(const int* __restrict__ deg, int* __restrict__ rowptr,
                             int* __restrict__ cursor, int n) {
    const int T = 1024;
    int tid = threadIdx.x;
    int chunk = (n + T - 1) / T;
    int start = tid * chunk;
    int end = min(start + chunk, n);
    if (start > n) start = n;
    if (end < start) end = start;

    int s = 0;
    for (int i = start; i < end; i++) s += deg[i] - 1;   // CSR excludes self loop

    __shared__ int warpsum[32];
    int lane = tid & 31, wid = tid >> 5;
    int v = s;
#pragma unroll
    for (int o = 1; o < 32; o <<= 1) {
        int t = __shfl_up_sync(0xffffffffu, v, o);
        if (lane >= o) v += t;
    }
    if (lane == 31) warpsum[wid] = v;
    __syncthreads();
    if (wid == 0) {
        int w = warpsum[lane];
#pragma unroll
        for (int o = 1; o < 32; o <<= 1) {
            int t = __shfl_up_sync(0xffffffffu, w, o);
            if (lane >= o) w += t;
        }
        warpsum[lane] = w;
    }
    __syncthreads();
    int excl = (v - s) + (wid > 0 ? warpsum[wid - 1] : 0);

    int run = excl;
    for (int i = start; i < end; i++) {
        rowptr[i] = run;
        cursor[i] = run;
        run += deg[i] - 1;
    }
    if (start < n && end == n) rowptr[n] = run;
}

__global__ void k_scatter(const int* __restrict__ src, const int* __restrict__ dst,
                          const float* __restrict__ dinv,
                          int* cursor, int* __restrict__ col, float* __restrict__ nrm, int E) {
    int e = blockIdx.x * blockDim.x + threadIdx.x;
    if (e >= E) return;
    int s = src[e], d = dst[e];
    int pos = atomicAdd(&cursor[d], 1);
    col[pos] = s;
    nrm[pos] = dinv[s] * dinv[d];
}

// ---------------- weight fake-quant (symmetric 4-bit) ----------------
__global__ void k_quant_w(const float* __restrict__ W, const float* __restrict__ a,
                          float* __restrict__ Wq, int n) {
    int i = blockIdx.x * blockDim.x + threadIdx.x;
    if (i >= n) return;
    float s = a[0];
    float v = fminf(fmaxf(W[i] / s, -8.0f), 7.0f);
    Wq[i] = rintf(v) * s;
}

// ---------------- GEMM: warp per row; optional fused BN+ReLU+feature fake-quant ----
template <bool FUSE>
__global__ void k_gemm(const float* __restrict__ X, const float* __restrict__ W,
                       const float* __restrict__ B, float* __restrict__ out,
                       const float* __restrict__ sc, const float* __restrict__ gq,
                       int N, int NC) {
    int warp = (blockIdx.x * blockDim.x + threadIdx.x) >> 5;
    int lane = threadIdx.x & 31;
    if (warp >= N) return;
    const float* xr = X + (size_t)warp * KDIM;
    float xv[4];
    xv[0] = xr[lane]; xv[1] = xr[lane + 32]; xv[2] = xr[lane + 64]; xv[3] = xr[lane + 96];
    if (FUSE) {
        float g = gq[warp];
#pragma unroll
        for (int i = 0; i < 4; i++) {
            int c = lane + 32 * i;
            float v = fmaxf(fmaf(xv[i], sc[c], sc[KDIM + c]), 0.f);  // BN + ReLU
            float u = fminf(v / g, 15.0f);                            // unsigned 4-bit
            xv[i] = rintf(u) * g;
        }
    }
    bool active = (lane * 4) < NC;
    int col = active ? lane * 4 : 0;
    float ax = 0.f, ay = 0.f, az = 0.f, aw = 0.f;
#pragma unroll
    for (int k = 0; k < KDIM; k++) {
        float s = (k < 32) ? xv[0] : (k < 64) ? xv[1] : (k < 96) ? xv[2] : xv[3];
        float xk = __shfl_sync(0xffffffffu, s, k & 31);
        float4 w = *(const float4*)(W + (size_t)k * NC + col);
        ax = fmaf(xk, w.x, ax); ay = fmaf(xk, w.y, ay);
        az = fmaf(xk, w.z, az); aw = fmaf(xk, w.w, aw);
    }
    if (active) {
        float4 bb = *(const float4*)(B + col);
        float* o = out + (size_t)warp * NC + col;
        o[0] = ax + bb.x; o[1] = ay + bb.y; o[2] = az + bb.z; o[3] = aw + bb.w;
    }
}

// ---------------- CSR aggregation, C=128: warp per dst node, self loop fused ------
__global__ void k_agg_csr128(const int* __restrict__ rowptr, const int* __restrict__ col,
                             const float* __restrict__ nrm, const float* __restrict__ dinv,
                             const float* __restrict__ in, float* __restrict__ out, int n) {
    int node = (blockIdx.x * blockDim.x + threadIdx.x) >> 5;
    int lane = threadIdx.x & 31;
    if (node >= n) return;
    int beg = rowptr[node], end = rowptr[node + 1];
    float dd = dinv[node]; dd *= dd;
    float4 v = __ldg((const float4*)(in + (size_t)node * KDIM) + lane);
    float4 acc = make_float4(dd * v.x, dd * v.y, dd * v.z, dd * v.w);
    int j = beg;
    for (; j + 2 <= end; j += 2) {
        int   s0 = __ldg(col + j),     s1 = __ldg(col + j + 1);
        float w0 = __ldg(nrm + j),     w1 = __ldg(nrm + j + 1);
        float4 m0 = __ldg((const float4*)(in + (size_t)s0 * KDIM) + lane);
        float4 m1 = __ldg((const float4*)(in + (size_t)s1 * KDIM) + lane);
        acc.x = fmaf(w0, m0.x, fmaf(w1, m1.x, acc.x));
        acc.y = fmaf(w0, m0.y, fmaf(w1, m1.y, acc.y));
        acc.z = fmaf(w0, m0.z, fmaf(w1, m1.z, acc.z));
        acc.w = fmaf(w0, m0.w, fmaf(w1, m1.w, acc.w));
    }
    if (j < end) {
        int s0 = __ldg(col + j); float w0 = __ldg(nrm + j);
        float4 m0 = __ldg((const float4*)(in + (size_t)s0 * KDIM) + lane);
        acc.x = fmaf(w0, m0.x, acc.x); acc.y = fmaf(w0, m0.y, acc.y);
        acc.z = fmaf(w0, m0.z, acc.z); acc.w = fmaf(w0, m0.w, acc.w);
    }
    *((float4*)(out + (size_t)node * KDIM) + lane) = acc;
}

// ---- CSR aggregation C=40 with fused log-softmax: warp per node ----
__global__ void k_agg40_lsm(const int* __restrict__ rowptr, const int* __restrict__ col,
                            const float* __restrict__ nrm, const float* __restrict__ dinv,
                            const float* __restrict__ in, float* __restrict__ out, int n) {
    int node = (blockIdx.x * blockDim.x + threadIdx.x) >> 5;
    int lane = threadIdx.x & 31;
    if (node >= n) return;
    int beg = rowptr[node], end = rowptr[node + 1];
    float dd = dinv[node]; dd *= dd;
    const float* r0 = in + (size_t)node * COUT;
    float accA = dd * __ldg(r0 + lane);
    float accB = (lane < 8) ? dd * __ldg(r0 + 32 + lane) : 0.f;
    for (int j = beg; j < end; j++) {
        int s = __ldg(col + j); float w = __ldg(nrm + j);
        const float* rs = in + (size_t)s * COUT;
        accA = fmaf(w, __ldg(rs + lane), accA);
        if (lane < 8) accB = fmaf(w, __ldg(rs + 32 + lane), accB);
    }
    // log-softmax over the 40 values held by this warp
    float b = (lane < 8) ? accB : -INFINITY;
    float m = fmaxf(accA, b);
#pragma unroll
    for (int o = 16; o > 0; o >>= 1) m = fmaxf(m, __shfl_xor_sync(0xffffffffu, m, o));
    float s = expf(accA - m) + ((lane < 8) ? expf(accB - m) : 0.f);
#pragma unroll
    for (int o = 16; o > 0; o >>= 1) s += __shfl_xor_sync(0xffffffffu, s, o);
    float ls = logf(s);
    float* w = out + (size_t)node * COUT;
    w[lane] = accA - m - ls;
    if (lane < 8) w[32 + lane] = accB - m - ls;
}

// ---------------- batch norm ----------------
__global__ void k_zero_stats(float* stats) {
    int i = threadIdx.x;
    if (i < 2 * KDIM) stats[i] = 0.f;
}

__global__ void k_bn_stats(const float* __restrict__ in, float* stats, int n) {
    int c = threadIdx.x;  // blockDim = 128
    float s = 0.f, sq = 0.f;
    for (int r = blockIdx.x; r < n; r += gridDim.x) {
        float v = in[(size_t)r * KDIM + c];
        s += v; sq = fmaf(v, v, sq);
    }
    atomicAdd(&stats[c], s);
    atomicAdd(&stats[KDIM + c], sq);
}

__global__ void k_bn_finalize(const float* __restrict__ stats,
                              const float* __restrict__ g, const float* __restrict__ b,
                              float* sc, int n) {
    int c = threadIdx.x;  // blockDim = 128
    float inv_n = 1.0f / (float)n;
    float mean = stats[c] * inv_n;
    float var  = stats[KDIM + c] * inv_n - mean * mean;
    float scale = g[c] * rsqrtf(var + BN_EPS);
    sc[c] = scale;
    sc[KDIM + c] = b[c] - mean * scale;
}

// ---------------- host ----------------
static inline int cdiv(int a, int b) { return (a + b - 1) / b; }

extern "C" void kernel_launch(void* const* d_in, const int* in_sizes, int n_in,
                              void* d_out, int out_size) {
    const float* x    = (const float*)d_in[0];
    const int*   ei   = (const int*)d_in[1];
    const float* W1   = (const float*)d_in[2];
    const float* b1   = (const float*)d_in[3];
    const float* a1   = (const float*)d_in[4];
    const float* W2   = (const float*)d_in[5];
    const float* b2   = (const float*)d_in[6];
    const float* a2   = (const float*)d_in[7];
    const float* g2   = (const float*)d_in[8];
    const float* W3   = (const float*)d_in[9];
    const float* b3   = (const float*)d_in[10];
    const float* a3   = (const float*)d_in[11];
    const float* g3   = (const float*)d_in[12];
    const float* bn1g = (const float*)d_in[13];
    const float* bn1b = (const float*)d_in[14];
    const float* bn2g = (const float*)d_in[15];
    const float* bn2b = (const float*)d_in[16];

    const int N = in_sizes[0] / KDIM;
    const int E = in_sizes[1] / 2;
    const int* src = ei;
    const int* dst = ei + E;

    float *buf1, *buf2, *dinv, *Wq, *stats, *sc, *nrm;
    int *deg, *rowptr, *cursor, *col;
    cudaGetSymbolAddress((void**)&buf1,   g_buf1);
    cudaGetSymbolAddress((void**)&buf2,   g_buf2);
    cudaGetSymbolAddress((void**)&dinv,   g_dinv);
    cudaGetSymbolAddress((void**)&deg,    g_deg);
    cudaGetSymbolAddress((void**)&rowptr, g_rowptr);
    cudaGetSymbolAddress((void**)&cursor, g_cursor);
    cudaGetSymbolAddress((void**)&col,    g_col);
    cudaGetSymbolAddress((void**)&nrm,    g_norm);
    cudaGetSymbolAddress((void**)&Wq,     g_Wq);
    cudaGetSymbolAddress((void**)&stats,  g_stats);
    cudaGetSymbolAddress((void**)&sc,     g_sc);

    const int TB = 256;

    // graph preprocessing: degrees, dinv, CSR
    k_init_deg<<<cdiv(N, TB), TB>>>(deg, N);
    k_count_deg<<<cdiv(E, TB), TB>>>(dst, deg, E);
    k_dinv<<<cdiv(N, TB), TB>>>(deg, dinv, N);
    k_scan_build<<<1, 1024>>>(deg, rowptr, cursor, N);
    k_scatter<<<cdiv(E, TB), TB>>>(src, dst, dinv, cursor, col, nrm, E);

    // ---- layer 1 ----
    k_quant_w<<<cdiv(KDIM * KDIM, TB), TB>>>(W1, a1, Wq, KDIM * KDIM);
    k_gemm<false><<<cdiv(N * 32, TB), TB>>>(x, Wq, b1, buf1, nullptr, nullptr, N, KDIM);
    k_agg_csr128<<<cdiv(N * 32, TB), TB>>>(rowptr, col, nrm, dinv, buf1, buf2, N);
    k_zero_stats<<<1, 256>>>(stats);
    k_bn_stats<<<512, 128>>>(buf2, stats, N);
    k_bn_finalize<<<1, 128>>>(stats, bn1g, bn1b, sc, N);

    // ---- layer 2 (BN+ReLU+fq fused into GEMM prologue) ----
    k_quant_w<<<cdiv(KDIM * KDIM, TB), TB>>>(W2, a2, Wq, KDIM * KDIM);
    k_gemm<true><<<cdiv(N * 32, TB), TB>>>(buf2, Wq, b2, buf1, sc, g2, N, KDIM);
    k_agg_csr128<<<cdiv(N * 32, TB), TB>>>(rowptr, col, nrm, dinv, buf1, buf2, N);
    k_zero_stats<<<1, 256>>>(stats);
    k_bn_stats<<<512, 128>>>(buf2, stats, N);
    k_bn_finalize<<<1, 128>>>(stats, bn2g, bn2b, sc, N);

    // ---- layer 3 (output, C=40; log-softmax fused into aggregation) ----
    k_quant_w<<<cdiv(KDIM * COUT, TB), TB>>>(W3, a3, Wq, KDIM * COUT);
    k_gemm<true><<<cdiv(N * 32, TB), TB>>>(buf2, Wq, b3, buf1, sc, g3, N, COUT);
    k_agg40_lsm<<<cdiv(N * 32, TB), TB>>>(rowptr, col, nrm, dinv, buf1, (float*)d_out, N);
}

// round 3
// speedup vs baseline: 1.6824x; 1.4134x over previous
#include <cuda_runtime.h>
#include <math.h>

#define NMAX   50000
#define EMAX   800000
#define KDIM   128
#define COUT   40
#define BN_EPS 1e-5f

#define SCAN_B 64
#define SCAN_T 256

#define TROWS  64   // gemm tile rows
#define KC     64   // gemm k-chunk

// ---------------- scratch (static device globals; no allocation) ----------------
__device__ float g_buf1[NMAX * KDIM];
__device__ float g_buf2[NMAX * KDIM];
__device__ float g_dinv[NMAX];
__device__ int   g_deg [NMAX];
__device__ int   g_rowptr[NMAX + 1];
__device__ int   g_cursor[NMAX];
__device__ int   g_col [EMAX];
__device__ float g_norm[EMAX];
__device__ float g_Wq  [KDIM * KDIM];
__device__ float g_stats[2 * KDIM];
__device__ float g_sc   [2 * KDIM];
__device__ int   g_tpref[SCAN_B * SCAN_T];
__device__ int   g_bsum [SCAN_B];

// ---------------- degree / norm ----------------
__global__ void k_init_deg(int* deg, int n) {
    int i = blockIdx.x * blockDim.x + threadIdx.x;
    if (i < n) deg[i] = 1;  // self loop
}

__global__ void k_count_deg(const int* __restrict__ dst, int* deg, int E) {
    int e = blockIdx.x * blockDim.x + threadIdx.x;
    if (e < E) atomicAdd(&deg[dst[e]], 1);
}

__global__ void k_dinv(const int* __restrict__ deg, float* dinv, int n) {
    int i = blockIdx.x * blockDim.x + threadIdx.x;
    if (i < n) dinv[i] = rsqrtf((float)deg[i]);
}

// ---------------- parallel CSR scan (3 phases) ----------------
__device__ __forceinline__ void chunk_range(int n, int b, int t, int& s, int& e) {
    int chunkB = (n + SCAN_B - 1) / SCAN_B;
    int bstart = b * chunkB;
    int bend = min(bstart + chunkB, n);
    int chunkT = (chunkB + SCAN_T - 1) / SCAN_T;
    s = min(bstart + t * chunkT, bend);
    e = min(s + chunkT, bend);
}

__global__ void k_scan_p1(const int* __restrict__ deg, int* __restrict__ tpref,
                          int* __restrict__ bsum, int n) {
    int b = blockIdx.x, t = threadIdx.x;
    int s, e; chunk_range(n, b, t, s, e);
    int acc = 0;
    for (int i = s; i < e; i++) acc += deg[i] - 1;

    int lane = t & 31, wid = t >> 5;
    int v = acc;
#pragma unroll
    for (int o = 1; o < 32; o <<= 1) {
        int u = __shfl_up_sync(0xffffffffu, v, o);
        if (lane >= o) v += u;
    }
    __shared__ int ws[8];
    if (lane == 31) ws[wid] = v;
    __syncthreads();
    if (t < 8) {
        int w = ws[t];
#pragma unroll
        for (int o = 1; o < 8; o <<= 1) {
            int u = __shfl_up_sync(0xffu, w, o);
            if (t >= o) w += u;
        }
        ws[t] = w;
    }
    __syncthreads();
    int excl = (v - acc) + (wid > 0 ? ws[wid - 1] : 0);
    tpref[b * SCAN_T + t] = excl;
    if (t == SCAN_T - 1) bsum[b] = excl + acc;
}

__global__ void k_scan_p2(int* bsum) {
    int t = threadIdx.x;  // SCAN_B = 64
    int orig = bsum[t];
    int lane = t & 31, w = t >> 5;
    int v = orig;
#pragma unroll
    for (int o = 1; o < 32; o <<= 1) {
        int u = __shfl_up_sync(0xffffffffu, v, o);
        if (lane >= o) v += u;
    }
    __shared__ int w0total;
    if (t == 31) w0total = v;
    __syncthreads();
    int excl = v - orig + (w == 1 ? w0total : 0);
    bsum[t] = excl;
}

__global__ void k_scan_p3(const int* __restrict__ deg, const int* __restrict__ tpref,
                          const int* __restrict__ bsum, int* __restrict__ rowptr,
                          int* __restrict__ cursor, int n, int E) {
    int b = blockIdx.x, t = threadIdx.x;
    int s, e; chunk_range(n, b, t, s, e);
    int run = bsum[b] + tpref[b * SCAN_T + t];
    for (int i = s; i < e; i++) {
        rowptr[i] = run;
        cursor[i] = run;
        run += deg[i] - 1;
    }
    if (b == 0 && t == 0) rowptr[n] = E;
}

__global__ void k_scatter(const int* __restrict__ src, const int* __restrict__ dst,
                          const float* __restrict__ dinv,
                          int* cursor, int* __restrict__ col, float* __restrict__ nrm, int E) {
    int e = blockIdx.x * blockDim.x + threadIdx.x;
    if (e >= E) return;
    int s = src[e], d = dst[e];
    int pos = atomicAdd(&cursor[d], 1);
    col[pos] = s;
    nrm[pos] = dinv[s] * dinv[d];
}

// ---------------- weight fake-quant (symmetric 4-bit) ----------------
__global__ void k_quant_w(const float* __restrict__ W, const float* __restrict__ a,
                          float* __restrict__ Wq, int n) {
    int i = blockIdx.x * blockDim.x + threadIdx.x;
    if (i >= n) return;
    float s = a[0];
    float v = fminf(fmaxf(W[i] / s, -8.0f), 7.0f);
    Wq[i] = rintf(v) * s;
}

// ---------------- tiled GEMM, NC=128: 64-row x 128-col tile, 8x4 per thread ------
template <bool FUSE>
__global__ __launch_bounds__(256) void k_gemm_tiled(
        const float* __restrict__ X, const float* __restrict__ W,
        const float* __restrict__ B, float* __restrict__ out,
        const float* __restrict__ sc, const float* __restrict__ gq, int N) {
    __shared__ float Ws[KC][KDIM];    // 32KB
    __shared__ float Xs[TROWS][KC];   // 16KB
    int tid  = threadIdx.x;
    int lane = tid & 31;
    int rb   = (tid >> 5) * 8;        // 8 rows per warp slot
    int col  = lane * 4;
    int row0 = blockIdx.x * TROWS;

    float acc[8][4];
#pragma unroll
    for (int r = 0; r < 8; r++)
#pragma unroll
        for (int c = 0; c < 4; c++) acc[r][c] = 0.f;

    for (int kc = 0; kc < KDIM; kc += KC) {
        // W chunk: KC x 128 floats, coalesced float4
        for (int i = tid; i < KC * (KDIM / 4); i += 256) {
            int k = i >> 5, c4 = i & 31;
            ((float4*)&Ws[k][0])[c4] =
                ((const float4*)(W + (size_t)(kc + k) * KDIM))[c4];
        }
        // X tile: TROWS x KC floats, row-major (coalesced, conflict-free)
        for (int i = tid; i < TROWS * (KC / 4); i += 256) {
            int r = i / (KC / 4);
            int kq = i % (KC / 4);
            int grow = row0 + r;
            float4 v = make_float4(0.f, 0.f, 0.f, 0.f);
            if (grow < N) {
                v = *((const float4*)(X + (size_t)grow * KDIM + kc) + kq);
                if (FUSE) {
                    float g = gq[grow];
                    float vv[4] = {v.x, v.y, v.z, v.w};
#pragma unroll
                    for (int u = 0; u < 4; u++) {
                        int c = kc + kq * 4 + u;
                        float t = fmaxf(fmaf(vv[u], sc[c], sc[KDIM + c]), 0.f);
                        vv[u] = rintf(fminf(t / g, 15.f)) * g;
                    }
                    v = make_float4(vv[0], vv[1], vv[2], vv[3]);
                }
            }
            ((float4*)&Xs[r][0])[kq] = v;
        }
        __syncthreads();
#pragma unroll 8
        for (int k = 0; k < KC; k++) {
            float4 w = *(const float4*)&Ws[k][col];
            float xr[8];
#pragma unroll
            for (int r = 0; r < 8; r++) xr[r] = Xs[rb + r][k];
#pragma unroll
            for (int r = 0; r < 8; r++) {
                acc[r][0] = fmaf(xr[r], w.x, acc[r][0]);
                acc[r][1] = fmaf(xr[r], w.y, acc[r][1]);
                acc[r][2] = fmaf(xr[r], w.z, acc[r][2]);
                acc[r][3] = fmaf(xr[r], w.w, acc[r][3]);
            }
        }
        __syncthreads();
    }
    float4 bb = *(const float4*)(B + col);
#pragma unroll
    for (int r = 0; r < 8; r++) {
        int grow = row0 + rb + r;
        if (grow < N) {
            float4 o = make_float4(acc[r][0] + bb.x, acc[r][1] + bb.y,
                                   acc[r][2] + bb.z, acc[r][3] + bb.w);
            *((float4*)(out + (size_t)grow * KDIM + col)) = o;
        }
    }
}

// ---------------- warp-per-row GEMM (used for NC=40) ----------------
template <bool FUSE>
__global__ void k_gemm(const float* __restrict__ X, const float* __restrict__ W,
                       const float* __restrict__ B, float* __restrict__ out,
                       const float* __restrict__ sc, const float* __restrict__ gq,
                       int N, int NC) {
    int warp = (blockIdx.x * blockDim.x + threadIdx.x) >> 5;
    int lane = threadIdx.x & 31;
    if (warp >= N) return;
    const float* xr = X + (size_t)warp * KDIM;
    float xv[4];
    xv[0] = xr[lane]; xv[1] = xr[lane + 32]; xv[2] = xr[lane + 64]; xv[3] = xr[lane + 96];
    if (FUSE) {
        float g = gq[warp];
#pragma unroll
        for (int i = 0; i < 4; i++) {
            int c = lane + 32 * i;
            float v = fmaxf(fmaf(xv[i], sc[c], sc[KDIM + c]), 0.f);
            float u = fminf(v / g, 15.0f);
            xv[i] = rintf(u) * g;
        }
    }
    bool active = (lane * 4) < NC;
    int col = active ? lane * 4 : 0;
    float ax = 0.f, ay = 0.f, az = 0.f, aw = 0.f;
#pragma unroll
    for (int k = 0; k < KDIM; k++) {
        float s = (k < 32) ? xv[0] : (k < 64) ? xv[1] : (k < 96) ? xv[2] : xv[3];
        float xk = __shfl_sync(0xffffffffu, s, k & 31);
        float4 w = *(const float4*)(W + (size_t)k * NC + col);
        ax = fmaf(xk, w.x, ax); ay = fmaf(xk, w.y, ay);
        az = fmaf(xk, w.z, az); aw = fmaf(xk, w.w, aw);
    }
    if (active) {
        float4 bb = *(const float4*)(B + col);
        float* o = out + (size_t)warp * NC + col;
        o[0] = ax + bb.x; o[1] = ay + bb.y; o[2] = az + bb.z; o[3] = aw + bb.w;
    }
}

// ---------------- CSR aggregation, C=128: warp per dst node, self loop fused ------
__global__ void k_agg_csr128(const int* __restrict__ rowptr, const int* __restrict__ col,
                             const float* __restrict__ nrm, const float* __restrict__ dinv,
                             const float* __restrict__ in, float* __restrict__ out, int n) {
    int node = (blockIdx.x * blockDim.x + threadIdx.x) >> 5;
    int lane = threadIdx.x & 31;
    if (node >= n) return;
    int beg = rowptr[node], end = rowptr[node + 1];
    float dd = dinv[node]; dd *= dd;
    float4 v = __ldg((const float4*)(in + (size_t)node * KDIM) + lane);
    float4 acc = make_float4(dd * v.x, dd * v.y, dd * v.z, dd * v.w);
    int j = beg;
    for (; j + 2 <= end; j += 2) {
        int   s0 = __ldg(col + j),     s1 = __ldg(col + j + 1);
        float w0 = __ldg(nrm + j),     w1 = __ldg(nrm + j + 1);
        float4 m0 = __ldg((const float4*)(in + (size_t)s0 * KDIM) + lane);
        float4 m1 = __ldg((const float4*)(in + (size_t)s1 * KDIM) + lane);
        acc.x = fmaf(w0, m0.x, fmaf(w1, m1.x, acc.x));
        acc.y = fmaf(w0, m0.y, fmaf(w1, m1.y, acc.y));
        acc.z = fmaf(w0, m0.z, fmaf(w1, m1.z, acc.z));
        acc.w = fmaf(w0, m0.w, fmaf(w1, m1.w, acc.w));
    }
    if (j < end) {
        int s0 = __ldg(col + j); float w0 = __ldg(nrm + j);
        float4 m0 = __ldg((const float4*)(in + (size_t)s0 * KDIM) + lane);
        acc.x = fmaf(w0, m0.x, acc.x); acc.y = fmaf(w0, m0.y, acc.y);
        acc.z = fmaf(w0, m0.z, acc.z); acc.w = fmaf(w0, m0.w, acc.w);
    }
    *((float4*)(out + (size_t)node * KDIM) + lane) = acc;
}

// ---- CSR aggregation C=40 with fused log-softmax: warp per node ----
__global__ void k_agg40_lsm(const int* __restrict__ rowptr, const int* __restrict__ col,
                            const float* __restrict__ nrm, const float* __restrict__ dinv,
                            const float* __restrict__ in, float* __restrict__ out, int n) {
    int node = (blockIdx.x * blockDim.x + threadIdx.x) >> 5;
    int lane = threadIdx.x & 31;
    if (node >= n) return;
    int beg = rowptr[node], end = rowptr[node + 1];
    float dd = dinv[node]; dd *= dd;
    const float* r0 = in + (size_t)node * COUT;
    float accA = dd * __ldg(r0 + lane);
    float accB = (lane < 8) ? dd * __ldg(r0 + 32 + lane) : 0.f;
    for (int j = beg; j < end; j++) {
        int s = __ldg(col + j); float w = __ldg(nrm + j);
        const float* rs = in + (size_t)s * COUT;
        accA = fmaf(w, __ldg(rs + lane), accA);
        if (lane < 8) accB = fmaf(w, __ldg(rs + 32 + lane), accB);
    }
    float b = (lane < 8) ? accB : -INFINITY;
    float m = fmaxf(accA, b);
#pragma unroll
    for (int o = 16; o > 0; o >>= 1) m = fmaxf(m, __shfl_xor_sync(0xffffffffu, m, o));
    float s = expf(accA - m) + ((lane < 8) ? expf(accB - m) : 0.f);
#pragma unroll
    for (int o = 16; o > 0; o >>= 1) s += __shfl_xor_sync(0xffffffffu, s, o);
    float ls = logf(s);
    float* w = out + (size_t)node * COUT;
    w[lane] = accA - m - ls;
    if (lane < 8) w[32 + lane] = accB - m - ls;
}

// ---------------- batch norm ----------------
__global__ void k_zero_stats(float* stats) {
    int i = threadIdx.x;
    if (i < 2 * KDIM) stats[i] = 0.f;
}

__global__ void k_bn_stats(const float* __restrict__ in, float* stats, int n) {
    int c = threadIdx.x;  // blockDim = 128
    float s = 0.f, sq = 0.f;
    for (int r = blockIdx.x; r < n; r += gridDim.x) {
        float v = in[(size_t)r * KDIM + c];
        s += v; sq = fmaf(v, v, sq);
    }
    atomicAdd(&stats[c], s);
    atomicAdd(&stats[KDIM + c], sq);
}

__global__ void k_bn_finalize(const float* __restrict__ stats,
                              const float* __restrict__ g, const float* __restrict__ b,
                              float* sc, int n) {
    int c = threadIdx.x;  // blockDim = 128
    float inv_n = 1.0f / (float)n;
    float mean = stats[c] * inv_n;
    float var  = stats[KDIM + c] * inv_n - mean * mean;
    float scale = g[c] * rsqrtf(var + BN_EPS);
    sc[c] = scale;
    sc[KDIM + c] = b[c] - mean * scale;
}

// ---------------- host ----------------
static inline int cdiv(int a, int b) { return (a + b - 1) / b; }

extern "C" void kernel_launch(void* const* d_in, const int* in_sizes, int n_in,
                              void* d_out, int out_size) {
    const float* x    = (const float*)d_in[0];
    const int*   ei   = (const int*)d_in[1];
    const float* W1   = (const float*)d_in[2];
    const float* b1   = (const float*)d_in[3];
    const float* a1   = (const float*)d_in[4];
    const float* W2   = (const float*)d_in[5];
    const float* b2   = (const float*)d_in[6];
    const float* a2   = (const float*)d_in[7];
    const float* g2   = (const float*)d_in[8];
    const float* W3   = (const float*)d_in[9];
    const float* b3   = (const float*)d_in[10];
    const float* a3   = (const float*)d_in[11];
    const float* g3   = (const float*)d_in[12];
    const float* bn1g = (const float*)d_in[13];
    const float* bn1b = (const float*)d_in[14];
    const float* bn2g = (const float*)d_in[15];
    const float* bn2b = (const float*)d_in[16];

    const int N = in_sizes[0] / KDIM;
    const int E = in_sizes[1] / 2;
    const int* src = ei;
    const int* dst = ei + E;

    float *buf1, *buf2, *dinv, *Wq, *stats, *sc, *nrm;
    int *deg, *rowptr, *cursor, *col, *tpref, *bsum;
    cudaGetSymbolAddress((void**)&buf1,   g_buf1);
    cudaGetSymbolAddress((void**)&buf2,   g_buf2);
    cudaGetSymbolAddress((void**)&dinv,   g_dinv);
    cudaGetSymbolAddress((void**)&deg,    g_deg);
    cudaGetSymbolAddress((void**)&rowptr, g_rowptr);
    cudaGetSymbolAddress((void**)&cursor, g_cursor);
    cudaGetSymbolAddress((void**)&col,    g_col);
    cudaGetSymbolAddress((void**)&nrm,    g_norm);
    cudaGetSymbolAddress((void**)&Wq,     g_Wq);
    cudaGetSymbolAddress((void**)&stats,  g_stats);
    cudaGetSymbolAddress((void**)&sc,     g_sc);
    cudaGetSymbolAddress((void**)&tpref,  g_tpref);
    cudaGetSymbolAddress((void**)&bsum,   g_bsum);

    const int TB = 256;
    const int GB = cdiv(N, TROWS);

    // graph preprocessing: degrees, dinv, CSR (parallel scan)
    k_init_deg<<<cdiv(N, TB), TB>>>(deg, N);
    k_count_deg<<<cdiv(E, TB), TB>>>(dst, deg, E);
    k_dinv<<<cdiv(N, TB), TB>>>(deg, dinv, N);
    k_scan_p1<<<SCAN_B, SCAN_T>>>(deg, tpref, bsum, N);
    k_scan_p2<<<1, SCAN_B>>>(bsum);
    k_scan_p3<<<SCAN_B, SCAN_T>>>(deg, tpref, bsum, rowptr, cursor, N, E);
    k_scatter<<<cdiv(E, TB), TB>>>(src, dst, dinv, cursor, col, nrm, E);

    // ---- layer 1 ----
    k_quant_w<<<cdiv(KDIM * KDIM, TB), TB>>>(W1, a1, Wq, KDIM * KDIM);
    k_gemm_tiled<false><<<GB, 256>>>(x, Wq, b1, buf1, nullptr, nullptr, N);
    k_agg_csr128<<<cdiv(N * 32, TB), TB>>>(rowptr, col, nrm, dinv, buf1, buf2, N);
    k_zero_stats<<<1, 256>>>(stats);
    k_bn_stats<<<512, 128>>>(buf2, stats, N);
    k_bn_finalize<<<1, 128>>>(stats, bn1g, bn1b, sc, N);

    // ---- layer 2 (BN+ReLU+fq fused into GEMM X-tile load) ----
    k_quant_w<<<cdiv(KDIM * KDIM, TB), TB>>>(W2, a2, Wq, KDIM * KDIM);
    k_gemm_tiled<true><<<GB, 256>>>(buf2, Wq, b2, buf1, sc, g2, N);
    k_agg_csr128<<<cdiv(N * 32, TB), TB>>>(rowptr, col, nrm, dinv, buf1, buf2, N);
    k_zero_stats<<<1, 256>>>(stats);
    k_bn_stats<<<512, 128>>>(buf2, stats, N);
    k_bn_finalize<<<1, 128>>>(stats, bn2g, bn2b, sc, N);

    // ---- layer 3 (output, C=40; log-softmax fused into aggregation) ----
    k_quant_w<<<cdiv(KDIM * COUT, TB), TB>>>(W3, a3, Wq, KDIM * COUT);
    k_gemm<true><<<cdiv(N * 32, TB), TB>>>(buf2, Wq, b3, buf1, sc, g3, N, COUT);
    k_agg40_lsm<<<cdiv(N * 32, TB), TB>>>(rowptr, col, nrm, dinv, buf1, (float*)d_out, N);
}

// round 4
// speedup vs baseline: 1.8032x; 1.0718x over previous
#include <cuda_runtime.h>
#include <math.h>

#define NMAX   50000
#define EMAX   800000
#define KDIM   128
#define COUT   40
#define BN_EPS 1e-5f

#define SCAN_B 64
#define SCAN_T 256

#define TROWS  64   // gemm tile rows
#define KC     64   // gemm k-chunk

#define AGG_BLOCKS 592

// ---------------- scratch (static device globals; no allocation) ----------------
__device__ float g_buf1[NMAX * KDIM];
__device__ float g_buf2[NMAX * KDIM];
__device__ float g_dinv[NMAX];
__device__ int   g_deg [NMAX];
__device__ int   g_rowptr[NMAX + 1];
__device__ int   g_cursor[NMAX];
__device__ int   g_col [EMAX];
__device__ float g_norm[EMAX];
__device__ float g_Wq1 [KDIM * KDIM];
__device__ float g_Wq2 [KDIM * KDIM];
__device__ float g_Wq3 [KDIM * COUT];
__device__ float g_stats1[2 * KDIM];
__device__ float g_stats2[2 * KDIM];
__device__ float g_sc   [2 * KDIM];
__device__ int   g_tpref[SCAN_B * SCAN_T];
__device__ int   g_bsum [SCAN_B];

// ---------------- f32x2 packed math ----------------
__device__ __forceinline__ unsigned long long pack2(float x) {
    unsigned long long r;
    asm("mov.b64 %0, {%1, %1};" : "=l"(r) : "f"(x));
    return r;
}
__device__ __forceinline__ unsigned long long ffma2(unsigned long long a,
                                                    unsigned long long b,
                                                    unsigned long long c) {
    unsigned long long d;
    asm("fma.rn.f32x2 %0, %1, %2, %3;" : "=l"(d) : "l"(a), "l"(b), "l"(c));
    return d;
}

// ---------------- degree / norm / stats-zero ----------------
__global__ void k_init(int* deg, float* s1, float* s2, int n) {
    int i = blockIdx.x * blockDim.x + threadIdx.x;
    if (i < n) deg[i] = 1;  // self loop
    if (i < 2 * KDIM) { s1[i] = 0.f; s2[i] = 0.f; }
}

__global__ void k_count_deg(const int* __restrict__ dst, int* deg, int E) {
    int e = blockIdx.x * blockDim.x + threadIdx.x;
    if (e < E) atomicAdd(&deg[dst[e]], 1);
}

__global__ void k_dinv(const int* __restrict__ deg, float* dinv, int n) {
    int i = blockIdx.x * blockDim.x + threadIdx.x;
    if (i < n) dinv[i] = rsqrtf((float)deg[i]);
}

// ---------------- parallel CSR scan (3 phases) ----------------
__device__ __forceinline__ void chunk_range(int n, int b, int t, int& s, int& e) {
    int chunkB = (n + SCAN_B - 1) / SCAN_B;
    int bstart = b * chunkB;
    int bend = min(bstart + chunkB, n);
    int chunkT = (chunkB + SCAN_T - 1) / SCAN_T;
    s = min(bstart + t * chunkT, bend);
    e = min(s + chunkT, bend);
}

__global__ void k_scan_p1(const int* __restrict__ deg, int* __restrict__ tpref,
                          int* __restrict__ bsum, int n) {
    int b = blockIdx.x, t = threadIdx.x;
    int s, e; chunk_range(n, b, t, s, e);
    int acc = 0;
    for (int i = s; i < e; i++) acc += deg[i] - 1;

    int lane = t & 31, wid = t >> 5;
    int v = acc;
#pragma unroll
    for (int o = 1; o < 32; o <<= 1) {
        int u = __shfl_up_sync(0xffffffffu, v, o);
        if (lane >= o) v += u;
    }
    __shared__ int ws[8];
    if (lane == 31) ws[wid] = v;
    __syncthreads();
    if (t < 8) {
        int w = ws[t];
#pragma unroll
        for (int o = 1; o < 8; o <<= 1) {
            int u = __shfl_up_sync(0xffu, w, o);
            if (t >= o) w += u;
        }
        ws[t] = w;
    }
    __syncthreads();
    int excl = (v - acc) + (wid > 0 ? ws[wid - 1] : 0);
    tpref[b * SCAN_T + t] = excl;
    if (t == SCAN_T - 1) bsum[b] = excl + acc;
}

__global__ void k_scan_p2(int* bsum) {
    int t = threadIdx.x;  // SCAN_B = 64
    int orig = bsum[t];
    int lane = t & 31, w = t >> 5;
    int v = orig;
#pragma unroll
    for (int o = 1; o < 32; o <<= 1) {
        int u = __shfl_up_sync(0xffffffffu, v, o);
        if (lane >= o) v += u;
    }
    __shared__ int w0total;
    if (t == 31) w0total = v;
    __syncthreads();
    int excl = v - orig + (w == 1 ? w0total : 0);
    bsum[t] = excl;
}

__global__ void k_scan_p3(const int* __restrict__ deg, const int* __restrict__ tpref,
                          const int* __restrict__ bsum, int* __restrict__ rowptr,
                          int* __restrict__ cursor, int n, int E) {
    int b = blockIdx.x, t = threadIdx.x;
    int s, e; chunk_range(n, b, t, s, e);
    int run = bsum[b] + tpref[b * SCAN_T + t];
    for (int i = s; i < e; i++) {
        rowptr[i] = run;
        cursor[i] = run;
        run += deg[i] - 1;
    }
    if (b == 0 && t == 0) rowptr[n] = E;
}

__global__ void k_scatter(const int* __restrict__ src, const int* __restrict__ dst,
                          const float* __restrict__ dinv,
                          int* cursor, int* __restrict__ col, float* __restrict__ nrm, int E) {
    int e = blockIdx.x * blockDim.x + threadIdx.x;
    if (e >= E) return;
    int s = src[e], d = dst[e];
    int pos = atomicAdd(&cursor[d], 1);
    col[pos] = s;
    nrm[pos] = dinv[s] * dinv[d];
}

// ---------------- all three weight fake-quants in one launch ----------------
__global__ void k_quant_all(const float* __restrict__ W1, const float* __restrict__ a1,
                            const float* __restrict__ W2, const float* __restrict__ a2,
                            const float* __restrict__ W3, const float* __restrict__ a3,
                            float* __restrict__ Q1, float* __restrict__ Q2,
                            float* __restrict__ Q3) {
    int i = blockIdx.x * blockDim.x + threadIdx.x;
    const int n12 = KDIM * KDIM, n3 = KDIM * COUT;
    if (i < n12) {
        float s = a1[0];
        Q1[i] = rintf(fminf(fmaxf(W1[i] / s, -8.0f), 7.0f)) * s;
    } else if (i < 2 * n12) {
        int j = i - n12;
        float s = a2[0];
        Q2[j] = rintf(fminf(fmaxf(W2[j] / s, -8.0f), 7.0f)) * s;
    } else if (i < 2 * n12 + n3) {
        int j = i - 2 * n12;
        float s = a3[0];
        Q3[j] = rintf(fminf(fmaxf(W3[j] / s, -8.0f), 7.0f)) * s;
    }
}

// ---------------- tiled GEMM, NC=128: packed f32x2 FMA ----------------
template <bool FUSE>
__global__ __launch_bounds__(256) void k_gemm_tiled(
        const float* __restrict__ X, const float* __restrict__ W,
        const float* __restrict__ B, float* __restrict__ out,
        const float* __restrict__ sc, const float* __restrict__ gq, int N) {
    __shared__ float Ws[KC][KDIM];    // 32KB
    __shared__ float Xs[TROWS][KC];   // 16KB
    int tid  = threadIdx.x;
    int lane = tid & 31;
    int rb   = (tid >> 5) * 8;        // 8 rows per warp slot
    int col  = lane * 4;
    int row0 = blockIdx.x * TROWS;

    unsigned long long acc01[8], acc23[8];
#pragma unroll
    for (int r = 0; r < 8; r++) { acc01[r] = 0ull; acc23[r] = 0ull; }

    for (int kc = 0; kc < KDIM; kc += KC) {
        for (int i = tid; i < KC * (KDIM / 4); i += 256) {
            int k = i >> 5, c4 = i & 31;
            ((float4*)&Ws[k][0])[c4] =
                ((const float4*)(W + (size_t)(kc + k) * KDIM))[c4];
        }
        for (int i = tid; i < TROWS * (KC / 4); i += 256) {
            int r = i / (KC / 4);
            int kq = i % (KC / 4);
            int grow = row0 + r;
            float4 v = make_float4(0.f, 0.f, 0.f, 0.f);
            if (grow < N) {
                v = *((const float4*)(X + (size_t)grow * KDIM + kc) + kq);
                if (FUSE) {
                    float g = gq[grow];
                    float vv[4] = {v.x, v.y, v.z, v.w};
#pragma unroll
                    for (int u = 0; u < 4; u++) {
                        int c = kc + kq * 4 + u;
                        float t = fmaxf(fmaf(vv[u], sc[c], sc[KDIM + c]), 0.f);
                        vv[u] = rintf(fminf(t / g, 15.f)) * g;
                    }
                    v = make_float4(vv[0], vv[1], vv[2], vv[3]);
                }
            }
            ((float4*)&Xs[r][0])[kq] = v;
        }
        __syncthreads();
#pragma unroll 8
        for (int k = 0; k < KC; k++) {
            ulonglong2 wv = *(const ulonglong2*)&Ws[k][col];
#pragma unroll
            for (int r = 0; r < 8; r++) {
                unsigned long long xp = pack2(Xs[rb + r][k]);
                acc01[r] = ffma2(xp, wv.x, acc01[r]);
                acc23[r] = ffma2(xp, wv.y, acc23[r]);
            }
        }
        __syncthreads();
    }
    float4 bb = *(const float4*)(B + col);
#pragma unroll
    for (int r = 0; r < 8; r++) {
        int grow = row0 + rb + r;
        if (grow < N) {
            float4 o;
            o.x = __uint_as_float((unsigned)(acc01[r]))       + bb.x;
            o.y = __uint_as_float((unsigned)(acc01[r] >> 32)) + bb.y;
            o.z = __uint_as_float((unsigned)(acc23[r]))       + bb.z;
            o.w = __uint_as_float((unsigned)(acc23[r] >> 32)) + bb.w;
            *((float4*)(out + (size_t)grow * KDIM + col)) = o;
        }
    }
}

// ---------------- warp-per-row GEMM (NC=40) ----------------
template <bool FUSE>
__global__ void k_gemm(const float* __restrict__ X, const float* __restrict__ W,
                       const float* __restrict__ B, float* __restrict__ out,
                       const float* __restrict__ sc, const float* __restrict__ gq,
                       int N, int NC) {
    int warp = (blockIdx.x * blockDim.x + threadIdx.x) >> 5;
    int lane = threadIdx.x & 31;
    if (warp >= N) return;
    const float* xr = X + (size_t)warp * KDIM;
    float xv[4];
    xv[0] = xr[lane]; xv[1] = xr[lane + 32]; xv[2] = xr[lane + 64]; xv[3] = xr[lane + 96];
    if (FUSE) {
        float g = gq[warp];
#pragma unroll
        for (int i = 0; i < 4; i++) {
            int c = lane + 32 * i;
            float v = fmaxf(fmaf(xv[i], sc[c], sc[KDIM + c]), 0.f);
            float u = fminf(v / g, 15.0f);
            xv[i] = rintf(u) * g;
        }
    }
    bool active = (lane * 4) < NC;
    int col = active ? lane * 4 : 0;
    float ax = 0.f, ay = 0.f, az = 0.f, aw = 0.f;
#pragma unroll
    for (int k = 0; k < KDIM; k++) {
        float s = (k < 32) ? xv[0] : (k < 64) ? xv[1] : (k < 96) ? xv[2] : xv[3];
        float xk = __shfl_sync(0xffffffffu, s, k & 31);
        float4 w = *(const float4*)(W + (size_t)k * NC + col);
        ax = fmaf(xk, w.x, ax); ay = fmaf(xk, w.y, ay);
        az = fmaf(xk, w.z, az); aw = fmaf(xk, w.w, aw);
    }
    if (active) {
        float4 bb = *(const float4*)(B + col);
        float* o = out + (size_t)warp * NC + col;
        o[0] = ax + bb.x; o[1] = ay + bb.y; o[2] = az + bb.z; o[3] = aw + bb.w;
    }
}

// ---- CSR aggregation C=128, grid-stride warp/node, unroll-4, fused BN stats ----
__global__ __launch_bounds__(256) void k_agg_csr128_stats(
        const int* __restrict__ rowptr, const int* __restrict__ col,
        const float* __restrict__ nrm, const float* __restrict__ dinv,
        const float* __restrict__ in, float* __restrict__ out,
        float* __restrict__ stats, int n) {
    int tid = threadIdx.x;
    int lane = tid & 31;
    int warp0 = (blockIdx.x * blockDim.x + tid) >> 5;
    int nwarps = (gridDim.x * blockDim.x) >> 5;
    int c0 = lane * 4;

    __shared__ float ssum[KDIM], ssq[KDIM];
    if (tid < KDIM) { ssum[tid] = 0.f; ssq[tid] = 0.f; }
    __syncthreads();

    float lsum[4] = {0.f, 0.f, 0.f, 0.f};
    float lsq [4] = {0.f, 0.f, 0.f, 0.f};

    for (int node = warp0; node < n; node += nwarps) {
        int beg = rowptr[node], end = rowptr[node + 1];
        float dd = dinv[node]; dd *= dd;
        float4 v = __ldg((const float4*)(in + (size_t)node * KDIM) + lane);
        float4 acc = make_float4(dd * v.x, dd * v.y, dd * v.z, dd * v.w);
        int j = beg;
        for (; j + 4 <= end; j += 4) {
            int   s0 = __ldg(col + j),     s1 = __ldg(col + j + 1);
            int   s2 = __ldg(col + j + 2), s3 = __ldg(col + j + 3);
            float w0 = __ldg(nrm + j),     w1 = __ldg(nrm + j + 1);
            float w2 = __ldg(nrm + j + 2), w3 = __ldg(nrm + j + 3);
            float4 m0 = __ldg((const float4*)(in + (size_t)s0 * KDIM) + lane);
            float4 m1 = __ldg((const float4*)(in + (size_t)s1 * KDIM) + lane);
            float4 m2 = __ldg((const float4*)(in + (size_t)s2 * KDIM) + lane);
            float4 m3 = __ldg((const float4*)(in + (size_t)s3 * KDIM) + lane);
            acc.x = fmaf(w0, m0.x, fmaf(w1, m1.x, fmaf(w2, m2.x, fmaf(w3, m3.x, acc.x))));
            acc.y = fmaf(w0, m0.y, fmaf(w1, m1.y, fmaf(w2, m2.y, fmaf(w3, m3.y, acc.y))));
            acc.z = fmaf(w0, m0.z, fmaf(w1, m1.z, fmaf(w2, m2.z, fmaf(w3, m3.z, acc.z))));
            acc.w = fmaf(w0, m0.w, fmaf(w1, m1.w, fmaf(w2, m2.w, fmaf(w3, m3.w, acc.w))));
        }
        for (; j < end; j++) {
            int s0 = __ldg(col + j); float w0 = __ldg(nrm + j);
            float4 m0 = __ldg((const float4*)(in + (size_t)s0 * KDIM) + lane);
            acc.x = fmaf(w0, m0.x, acc.x); acc.y = fmaf(w0, m0.y, acc.y);
            acc.z = fmaf(w0, m0.z, acc.z); acc.w = fmaf(w0, m0.w, acc.w);
        }
        *((float4*)(out + (size_t)node * KDIM) + lane) = acc;
        lsum[0] += acc.x; lsum[1] += acc.y; lsum[2] += acc.z; lsum[3] += acc.w;
        lsq[0] = fmaf(acc.x, acc.x, lsq[0]); lsq[1] = fmaf(acc.y, acc.y, lsq[1]);
        lsq[2] = fmaf(acc.z, acc.z, lsq[2]); lsq[3] = fmaf(acc.w, acc.w, lsq[3]);
    }
#pragma unroll
    for (int u = 0; u < 4; u++) {
        atomicAdd(&ssum[c0 + u], lsum[u]);
        atomicAdd(&ssq [c0 + u], lsq[u]);
    }
    __syncthreads();
    if (tid < KDIM) {
        atomicAdd(&stats[tid], ssum[tid]);
        atomicAdd(&stats[KDIM + tid], ssq[tid]);
    }
}

// ---- CSR aggregation C=40 with fused log-softmax ----
__global__ void k_agg40_lsm(const int* __restrict__ rowptr, const int* __restrict__ col,
                            const float* __restrict__ nrm, const float* __restrict__ dinv,
                            const float* __restrict__ in, float* __restrict__ out, int n) {
    int node = (blockIdx.x * blockDim.x + threadIdx.x) >> 5;
    int lane = threadIdx.x & 31;
    if (node >= n) return;
    int beg = rowptr[node], end = rowptr[node + 1];
    float dd = dinv[node]; dd *= dd;
    const float* r0 = in + (size_t)node * COUT;
    float accA = dd * __ldg(r0 + lane);
    float accB = (lane < 8) ? dd * __ldg(r0 + 32 + lane) : 0.f;
    int j = beg;
    for (; j + 2 <= end; j += 2) {
        int s0 = __ldg(col + j), s1 = __ldg(col + j + 1);
        float w0 = __ldg(nrm + j), w1 = __ldg(nrm + j + 1);
        const float* rs0 = in + (size_t)s0 * COUT;
        const float* rs1 = in + (size_t)s1 * COUT;
        accA = fmaf(w0, __ldg(rs0 + lane), fmaf(w1, __ldg(rs1 + lane), accA));
        if (lane < 8)
            accB = fmaf(w0, __ldg(rs0 + 32 + lane), fmaf(w1, __ldg(rs1 + 32 + lane), accB));
    }
    if (j < end) {
        int s = __ldg(col + j); float w = __ldg(nrm + j);
        const float* rs = in + (size_t)s * COUT;
        accA = fmaf(w, __ldg(rs + lane), accA);
        if (lane < 8) accB = fmaf(w, __ldg(rs + 32 + lane), accB);
    }
    float b = (lane < 8) ? accB : -INFINITY;
    float m = fmaxf(accA, b);
#pragma unroll
    for (int o = 16; o > 0; o >>= 1) m = fmaxf(m, __shfl_xor_sync(0xffffffffu, m, o));
    float s = expf(accA - m) + ((lane < 8) ? expf(accB - m) : 0.f);
#pragma unroll
    for (int o = 16; o > 0; o >>= 1) s += __shfl_xor_sync(0xffffffffu, s, o);
    float ls = logf(s);
    float* w = out + (size_t)node * COUT;
    w[lane] = accA - m - ls;
    if (lane < 8) w[32 + lane] = accB - m - ls;
}

// ---------------- batch norm finalize ----------------
__global__ void k_bn_finalize(const float* __restrict__ stats,
                              const float* __restrict__ g, const float* __restrict__ b,
                              float* sc, int n) {
    int c = threadIdx.x;  // blockDim = 128
    float inv_n = 1.0f / (float)n;
    float mean = stats[c] * inv_n;
    float var  = stats[KDIM + c] * inv_n - mean * mean;
    float scale = g[c] * rsqrtf(var + BN_EPS);
    sc[c] = scale;
    sc[KDIM + c] = b[c] - mean * scale;
}

// ---------------- host ----------------
static inline int cdiv(int a, int b) { return (a + b - 1) / b; }

extern "C" void kernel_launch(void* const* d_in, const int* in_sizes, int n_in,
                              void* d_out, int out_size) {
    const float* x    = (const float*)d_in[0];
    const int*   ei   = (const int*)d_in[1];
    const float* W1   = (const float*)d_in[2];
    const float* b1   = (const float*)d_in[3];
    const float* a1   = (const float*)d_in[4];
    const float* W2   = (const float*)d_in[5];
    const float* b2   = (const float*)d_in[6];
    const float* a2   = (const float*)d_in[7];
    const float* g2   = (const float*)d_in[8];
    const float* W3   = (const float*)d_in[9];
    const float* b3   = (const float*)d_in[10];
    const float* a3   = (const float*)d_in[11];
    const float* g3   = (const float*)d_in[12];
    const float* bn1g = (const float*)d_in[13];
    const float* bn1b = (const float*)d_in[14];
    const float* bn2g = (const float*)d_in[15];
    const float* bn2b = (const float*)d_in[16];

    const int N = in_sizes[0] / KDIM;
    const int E = in_sizes[1] / 2;
    const int* src = ei;
    const int* dst = ei + E;

    float *buf1, *buf2, *dinv, *Wq1, *Wq2, *Wq3, *stats1, *stats2, *sc, *nrm;
    int *deg, *rowptr, *cursor, *col, *tpref, *bsum;
    cudaGetSymbolAddress((void**)&buf1,   g_buf1);
    cudaGetSymbolAddress((void**)&buf2,   g_buf2);
    cudaGetSymbolAddress((void**)&dinv,   g_dinv);
    cudaGetSymbolAddress((void**)&deg,    g_deg);
    cudaGetSymbolAddress((void**)&rowptr, g_rowptr);
    cudaGetSymbolAddress((void**)&cursor, g_cursor);
    cudaGetSymbolAddress((void**)&col,    g_col);
    cudaGetSymbolAddress((void**)&nrm,    g_norm);
    cudaGetSymbolAddress((void**)&Wq1,    g_Wq1);
    cudaGetSymbolAddress((void**)&Wq2,    g_Wq2);
    cudaGetSymbolAddress((void**)&Wq3,    g_Wq3);
    cudaGetSymbolAddress((void**)&stats1, g_stats1);
    cudaGetSymbolAddress((void**)&stats2, g_stats2);
    cudaGetSymbolAddress((void**)&sc,     g_sc);
    cudaGetSymbolAddress((void**)&tpref,  g_tpref);
    cudaGetSymbolAddress((void**)&bsum,   g_bsum);

    const int TB = 256;
    const int GB = cdiv(N, TROWS);
    const int QN = 2 * KDIM * KDIM + KDIM * COUT;

    // graph preprocessing + weight quant
    k_init<<<cdiv(N, TB), TB>>>(deg, stats1, stats2, N);
    k_count_deg<<<cdiv(E, TB), TB>>>(dst, deg, E);
    k_quant_all<<<cdiv(QN, TB), TB>>>(W1, a1, W2, a2, W3, a3, Wq1, Wq2, Wq3);
    k_dinv<<<cdiv(N, TB), TB>>>(deg, dinv, N);
    k_scan_p1<<<SCAN_B, SCAN_T>>>(deg, tpref, bsum, N);
    k_scan_p2<<<1, SCAN_B>>>(bsum);
    k_scan_p3<<<SCAN_B, SCAN_T>>>(deg, tpref, bsum, rowptr, cursor, N, E);
    k_scatter<<<cdiv(E, TB), TB>>>(src, dst, dinv, cursor, col, nrm, E);

    // ---- layer 1 ----
    k_gemm_tiled<false><<<GB, 256>>>(x, Wq1, b1, buf1, nullptr, nullptr, N);
    k_agg_csr128_stats<<<AGG_BLOCKS, 256>>>(rowptr, col, nrm, dinv, buf1, buf2, stats1, N);
    k_bn_finalize<<<1, 128>>>(stats1, bn1g, bn1b, sc, N);

    // ---- layer 2 (BN+ReLU+fq fused into GEMM X-tile load) ----
    k_gemm_tiled<true><<<GB, 256>>>(buf2, Wq2, b2, buf1, sc, g2, N);
    k_agg_csr128_stats<<<AGG_BLOCKS, 256>>>(rowptr, col, nrm, dinv, buf1, buf2, stats2, N);
    k_bn_finalize<<<1, 128>>>(stats2, bn2g, bn2b, sc, N);

    // ---- layer 3 (output, C=40; log-softmax fused into aggregation) ----
    k_gemm<true><<<cdiv(N * 32, TB), TB>>>(buf2, Wq3, b3, buf1, sc, g3, N, COUT);
    k_agg40_lsm<<<cdiv(N * 32, TB), TB>>>(rowptr, col, nrm, dinv, buf1, (float*)d_out, N);
}

// round 5
// speedup vs baseline: 1.9545x; 1.0839x over previous
#include <cuda_runtime.h>
#include <math.h>

#define NMAX   50000
#define EMAX   800000
#define KDIM   128
#define COUT   40
#define BN_EPS 1e-5f

#define SCAN_B 64
#define SCAN_T 256

#define TROWS  64   // gemm tile rows
#define KC     64   // gemm k-chunk

#define AGG_BLOCKS 592

// ---------------- scratch (static device globals; no allocation) ----------------
__device__ float g_buf1[NMAX * KDIM];
__device__ float g_buf2[NMAX * KDIM];
__device__ float g_dinv[NMAX];
__device__ int   g_deg [NMAX];
__device__ int   g_rowptr[NMAX + 1];
__device__ int   g_cursor[NMAX];
__device__ int2  g_edge[EMAX];          // {src, nrm bits}
__device__ float g_Wq1 [KDIM * KDIM];
__device__ float g_Wq2 [KDIM * KDIM];
__device__ float g_Wq3 [KDIM * COUT];
__device__ float g_stats1[2 * KDIM];
__device__ float g_stats2[2 * KDIM];
__device__ int   g_tpref[SCAN_B * SCAN_T];
__device__ int   g_bsum [SCAN_B];

// ---------------- f32x2 packed math ----------------
__device__ __forceinline__ unsigned long long pack2(float x) {
    unsigned long long r;
    asm("mov.b64 %0, {%1, %1};" : "=l"(r) : "f"(x));
    return r;
}
__device__ __forceinline__ unsigned long long ffma2(unsigned long long a,
                                                    unsigned long long b,
                                                    unsigned long long c) {
    unsigned long long d;
    asm("fma.rn.f32x2 %0, %1, %2, %3;" : "=l"(d) : "l"(a), "l"(b), "l"(c));
    return d;
}

// ------- init: deg=1, stats=0, and all three weight fake-quants, one launch -------
__global__ void k_init_quant(int* __restrict__ deg, float* __restrict__ s1,
                             float* __restrict__ s2,
                             const float* __restrict__ W1, const float* __restrict__ a1,
                             const float* __restrict__ W2, const float* __restrict__ a2,
                             const float* __restrict__ W3, const float* __restrict__ a3,
                             float* __restrict__ Q1, float* __restrict__ Q2,
                             float* __restrict__ Q3, int n) {
    int i = blockIdx.x * blockDim.x + threadIdx.x;
    if (i < n) deg[i] = 1;  // self loop
    if (i < 2 * KDIM) { s1[i] = 0.f; s2[i] = 0.f; }
    const int n12 = KDIM * KDIM, n3 = KDIM * COUT;
    if (i < n12) {
        float s = a1[0];
        Q1[i] = rintf(fminf(fmaxf(W1[i] / s, -8.0f), 7.0f)) * s;
        float s2v = a2[0];
        Q2[i] = rintf(fminf(fmaxf(W2[i] / s2v, -8.0f), 7.0f)) * s2v;
    }
    if (i < n3) {
        float s = a3[0];
        Q3[i] = rintf(fminf(fmaxf(W3[i] / s, -8.0f), 7.0f)) * s;
    }
}

__global__ void k_count_deg(const int* __restrict__ dst, int* deg, int E) {
    int e = blockIdx.x * blockDim.x + threadIdx.x;
    if (e < E) atomicAdd(&deg[dst[e]], 1);
}

// ---------------- parallel CSR scan (3 phases); p1 also computes dinv ----------------
__device__ __forceinline__ void chunk_range(int n, int b, int t, int& s, int& e) {
    int chunkB = (n + SCAN_B - 1) / SCAN_B;
    int bstart = b * chunkB;
    int bend = min(bstart + chunkB, n);
    int chunkT = (chunkB + SCAN_T - 1) / SCAN_T;
    s = min(bstart + t * chunkT, bend);
    e = min(s + chunkT, bend);
}

__global__ void k_scan_p1(const int* __restrict__ deg, float* __restrict__ dinv,
                          int* __restrict__ tpref, int* __restrict__ bsum, int n) {
    int b = blockIdx.x, t = threadIdx.x;
    int s, e; chunk_range(n, b, t, s, e);
    int acc = 0;
    for (int i = s; i < e; i++) {
        int d = deg[i];
        dinv[i] = rsqrtf((float)d);
        acc += d - 1;
    }
    int lane = t & 31, wid = t >> 5;
    int v = acc;
#pragma unroll
    for (int o = 1; o < 32; o <<= 1) {
        int u = __shfl_up_sync(0xffffffffu, v, o);
        if (lane >= o) v += u;
    }
    __shared__ int ws[8];
    if (lane == 31) ws[wid] = v;
    __syncthreads();
    if (t < 8) {
        int w = ws[t];
#pragma unroll
        for (int o = 1; o < 8; o <<= 1) {
            int u = __shfl_up_sync(0xffu, w, o);
            if (t >= o) w += u;
        }
        ws[t] = w;
    }
    __syncthreads();
    int excl = (v - acc) + (wid > 0 ? ws[wid - 1] : 0);
    tpref[b * SCAN_T + t] = excl;
    if (t == SCAN_T - 1) bsum[b] = excl + acc;
}

__global__ void k_scan_p2(int* bsum) {
    int t = threadIdx.x;  // SCAN_B = 64
    int orig = bsum[t];
    int lane = t & 31, w = t >> 5;
    int v = orig;
#pragma unroll
    for (int o = 1; o < 32; o <<= 1) {
        int u = __shfl_up_sync(0xffffffffu, v, o);
        if (lane >= o) v += u;
    }
    __shared__ int w0total;
    if (t == 31) w0total = v;
    __syncthreads();
    int excl = v - orig + (w == 1 ? w0total : 0);
    bsum[t] = excl;
}

__global__ void k_scan_p3(const int* __restrict__ deg, const int* __restrict__ tpref,
                          const int* __restrict__ bsum, int* __restrict__ rowptr,
                          int* __restrict__ cursor, int n, int E) {
    int b = blockIdx.x, t = threadIdx.x;
    int s, e; chunk_range(n, b, t, s, e);
    int run = bsum[b] + tpref[b * SCAN_T + t];
    for (int i = s; i < e; i++) {
        rowptr[i] = run;
        cursor[i] = run;
        run += deg[i] - 1;
    }
    if (b == 0 && t == 0) rowptr[n] = E;
}

__global__ void k_scatter(const int* __restrict__ src, const int* __restrict__ dst,
                          const float* __restrict__ dinv,
                          int* cursor, int2* __restrict__ edge, int E) {
    int e = blockIdx.x * blockDim.x + threadIdx.x;
    if (e >= E) return;
    int s = src[e], d = dst[e];
    int pos = atomicAdd(&cursor[d], 1);
    edge[pos] = make_int2(s, __float_as_int(dinv[s] * dinv[d]));
}

// ---------------- tiled GEMM, NC=128: packed f32x2 FMA, 2-k inner step ----------
// FUSE: computes BN scale/shift from raw stats per block, then BN+ReLU+4-bit fq.
template <bool FUSE>
__global__ __launch_bounds__(256) void k_gemm_tiled(
        const float* __restrict__ X, const float* __restrict__ W,
        const float* __restrict__ B, float* __restrict__ out,
        const float* __restrict__ stats, const float* __restrict__ bng,
        const float* __restrict__ bnb, const float* __restrict__ gq, int N) {
    __shared__ float Ws[KC][KDIM];    // 32KB
    __shared__ float Xs[TROWS][KC];   // 16KB
    __shared__ float scs[2 * KDIM];
    int tid  = threadIdx.x;
    int lane = tid & 31;
    int rb   = (tid >> 5) * 8;
    int col  = lane * 4;
    int row0 = blockIdx.x * TROWS;

    if (FUSE) {
        if (tid < KDIM) {
            float inv_n = 1.0f / (float)N;
            float mean = stats[tid] * inv_n;
            float var  = stats[KDIM + tid] * inv_n - mean * mean;
            float scale = bng[tid] * rsqrtf(var + BN_EPS);
            scs[tid] = scale;
            scs[KDIM + tid] = bnb[tid] - mean * scale;
        }
        __syncthreads();
    }

    unsigned long long acc01[8], acc23[8];
#pragma unroll
    for (int r = 0; r < 8; r++) { acc01[r] = 0ull; acc23[r] = 0ull; }

    for (int kc = 0; kc < KDIM; kc += KC) {
        for (int i = tid; i < KC * (KDIM / 4); i += 256) {
            int k = i >> 5, c4 = i & 31;
            ((float4*)&Ws[k][0])[c4] =
                ((const float4*)(W + (size_t)(kc + k) * KDIM))[c4];
        }
        for (int i = tid; i < TROWS * (KC / 4); i += 256) {
            int r = i / (KC / 4);
            int kq = i % (KC / 4);
            int grow = row0 + r;
            float4 v = make_float4(0.f, 0.f, 0.f, 0.f);
            if (grow < N) {
                v = *((const float4*)(X + (size_t)grow * KDIM + kc) + kq);
                if (FUSE) {
                    float g = gq[grow];
                    float vv[4] = {v.x, v.y, v.z, v.w};
#pragma unroll
                    for (int u = 0; u < 4; u++) {
                        int c = kc + kq * 4 + u;
                        float t = fmaxf(fmaf(vv[u], scs[c], scs[KDIM + c]), 0.f);
                        vv[u] = rintf(fminf(t / g, 15.f)) * g;
                    }
                    v = make_float4(vv[0], vv[1], vv[2], vv[3]);
                }
            }
            ((float4*)&Xs[r][0])[kq] = v;
        }
        __syncthreads();
#pragma unroll 4
        for (int k = 0; k < KC; k += 2) {
            ulonglong2 w0 = *(const ulonglong2*)&Ws[k][col];
            ulonglong2 w1 = *(const ulonglong2*)&Ws[k + 1][col];
#pragma unroll
            for (int r = 0; r < 8; r++) {
                float2 xp = *(const float2*)&Xs[rb + r][k];   // LDS.64 broadcast
                unsigned long long xa = pack2(xp.x);
                unsigned long long xb = pack2(xp.y);
                acc01[r] = ffma2(xa, w0.x, acc01[r]);
                acc23[r] = ffma2(xa, w0.y, acc23[r]);
                acc01[r] = ffma2(xb, w1.x, acc01[r]);
                acc23[r] = ffma2(xb, w1.y, acc23[r]);
            }
        }
        __syncthreads();
    }
    float4 bb = *(const float4*)(B + col);
#pragma unroll
    for (int r = 0; r < 8; r++) {
        int grow = row0 + rb + r;
        if (grow < N) {
            float4 o;
            o.x = __uint_as_float((unsigned)(acc01[r]))       + bb.x;
            o.y = __uint_as_float((unsigned)(acc01[r] >> 32)) + bb.y;
            o.z = __uint_as_float((unsigned)(acc23[r]))       + bb.z;
            o.w = __uint_as_float((unsigned)(acc23[r] >> 32)) + bb.w;
            *((float4*)(out + (size_t)grow * KDIM + col)) = o;
        }
    }
}

// ---------------- warp-per-row GEMM (NC=40), fused BN+ReLU+fq prologue ----------
__global__ __launch_bounds__(256) void k_gemm40(
        const float* __restrict__ X, const float* __restrict__ W,
        const float* __restrict__ B, float* __restrict__ out,
        const float* __restrict__ stats, const float* __restrict__ bng,
        const float* __restrict__ bnb, const float* __restrict__ gq, int N) {
    __shared__ float scs[2 * KDIM];
    int tid = threadIdx.x;
    if (tid < KDIM) {
        float inv_n = 1.0f / (float)N;
        float mean = stats[tid] * inv_n;
        float var  = stats[KDIM + tid] * inv_n - mean * mean;
        float scale = bng[tid] * rsqrtf(var + BN_EPS);
        scs[tid] = scale;
        scs[KDIM + tid] = bnb[tid] - mean * scale;
    }
    __syncthreads();

    int warp = (blockIdx.x * blockDim.x + tid) >> 5;
    int lane = tid & 31;
    if (warp >= N) return;
    const float* xr = X + (size_t)warp * KDIM;
    float xv[4];
    float g = gq[warp];
#pragma unroll
    for (int i = 0; i < 4; i++) {
        int c = lane + 32 * i;
        float v = fmaxf(fmaf(xr[c], scs[c], scs[KDIM + c]), 0.f);
        xv[i] = rintf(fminf(v / g, 15.0f)) * g;
    }
    bool active = (lane * 4) < COUT;
    int col = active ? lane * 4 : 0;
    float ax = 0.f, ay = 0.f, az = 0.f, aw = 0.f;
#pragma unroll
    for (int k = 0; k < KDIM; k++) {
        float s = (k < 32) ? xv[0] : (k < 64) ? xv[1] : (k < 96) ? xv[2] : xv[3];
        float xk = __shfl_sync(0xffffffffu, s, k & 31);
        float4 w = *(const float4*)(W + (size_t)k * COUT + col);
        ax = fmaf(xk, w.x, ax); ay = fmaf(xk, w.y, ay);
        az = fmaf(xk, w.z, az); aw = fmaf(xk, w.w, aw);
    }
    if (active) {
        float4 bb = *(const float4*)(B + col);
        float* o = out + (size_t)warp * COUT + col;
        o[0] = ax + bb.x; o[1] = ay + bb.y; o[2] = az + bb.z; o[3] = aw + bb.w;
    }
}

// ---- CSR aggregation C=128, grid-stride warp/node, unroll-4, fused BN stats ----
__global__ __launch_bounds__(256) void k_agg_csr128_stats(
        const int* __restrict__ rowptr, const int2* __restrict__ edge,
        const float* __restrict__ dinv,
        const float* __restrict__ in, float* __restrict__ out,
        float* __restrict__ stats, int n) {
    int tid = threadIdx.x;
    int lane = tid & 31;
    int warp0 = (blockIdx.x * blockDim.x + tid) >> 5;
    int nwarps = (gridDim.x * blockDim.x) >> 5;
    int c0 = lane * 4;

    __shared__ float ssum[KDIM], ssq[KDIM];
    if (tid < KDIM) { ssum[tid] = 0.f; ssq[tid] = 0.f; }
    __syncthreads();

    float lsum[4] = {0.f, 0.f, 0.f, 0.f};
    float lsq [4] = {0.f, 0.f, 0.f, 0.f};

    for (int node = warp0; node < n; node += nwarps) {
        int beg = rowptr[node], end = rowptr[node + 1];
        float dd = dinv[node]; dd *= dd;
        float4 v = __ldg((const float4*)(in + (size_t)node * KDIM) + lane);
        float4 acc = make_float4(dd * v.x, dd * v.y, dd * v.z, dd * v.w);
        int j = beg;
        for (; j + 4 <= end; j += 4) {
            int2 e0 = __ldg(edge + j),     e1 = __ldg(edge + j + 1);
            int2 e2 = __ldg(edge + j + 2), e3 = __ldg(edge + j + 3);
            float w0 = __int_as_float(e0.y), w1 = __int_as_float(e1.y);
            float w2 = __int_as_float(e2.y), w3 = __int_as_float(e3.y);
            float4 m0 = __ldg((const float4*)(in + (size_t)e0.x * KDIM) + lane);
            float4 m1 = __ldg((const float4*)(in + (size_t)e1.x * KDIM) + lane);
            float4 m2 = __ldg((const float4*)(in + (size_t)e2.x * KDIM) + lane);
            float4 m3 = __ldg((const float4*)(in + (size_t)e3.x * KDIM) + lane);
            acc.x = fmaf(w0, m0.x, fmaf(w1, m1.x, fmaf(w2, m2.x, fmaf(w3, m3.x, acc.x))));
            acc.y = fmaf(w0, m0.y, fmaf(w1, m1.y, fmaf(w2, m2.y, fmaf(w3, m3.y, acc.y))));
            acc.z = fmaf(w0, m0.z, fmaf(w1, m1.z, fmaf(w2, m2.z, fmaf(w3, m3.z, acc.z))));
            acc.w = fmaf(w0, m0.w, fmaf(w1, m1.w, fmaf(w2, m2.w, fmaf(w3, m3.w, acc.w))));
        }
        for (; j < end; j++) {
            int2 e0 = __ldg(edge + j);
            float w0 = __int_as_float(e0.y);
            float4 m0 = __ldg((const float4*)(in + (size_t)e0.x * KDIM) + lane);
            acc.x = fmaf(w0, m0.x, acc.x); acc.y = fmaf(w0, m0.y, acc.y);
            acc.z = fmaf(w0, m0.z, acc.z); acc.w = fmaf(w0, m0.w, acc.w);
        }
        *((float4*)(out + (size_t)node * KDIM) + lane) = acc;
        lsum[0] += acc.x; lsum[1] += acc.y; lsum[2] += acc.z; lsum[3] += acc.w;
        lsq[0] = fmaf(acc.x, acc.x, lsq[0]); lsq[1] = fmaf(acc.y, acc.y, lsq[1]);
        lsq[2] = fmaf(acc.z, acc.z, lsq[2]); lsq[3] = fmaf(acc.w, acc.w, lsq[3]);
    }
#pragma unroll
    for (int u = 0; u < 4; u++) {
        atomicAdd(&ssum[c0 + u], lsum[u]);
        atomicAdd(&ssq [c0 + u], lsq[u]);
    }
    __syncthreads();
    if (tid < KDIM) {
        atomicAdd(&stats[tid], ssum[tid]);
        atomicAdd(&stats[KDIM + tid], ssq[tid]);
    }
}

// ---- CSR aggregation C=40 with fused log-softmax ----
__global__ void k_agg40_lsm(const int* __restrict__ rowptr, const int2* __restrict__ edge,
                            const float* __restrict__ dinv,
                            const float* __restrict__ in, float* __restrict__ out, int n) {
    int node = (blockIdx.x * blockDim.x + threadIdx.x) >> 5;
    int lane = threadIdx.x & 31;
    if (node >= n) return;
    int beg = rowptr[node], end = rowptr[node + 1];
    float dd = dinv[node]; dd *= dd;
    const float* r0 = in + (size_t)node * COUT;
    float accA = dd * __ldg(r0 + lane);
    float accB = (lane < 8) ? dd * __ldg(r0 + 32 + lane) : 0.f;
    int j = beg;
    for (; j + 2 <= end; j += 2) {
        int2 e0 = __ldg(edge + j), e1 = __ldg(edge + j + 1);
        float w0 = __int_as_float(e0.y), w1 = __int_as_float(e1.y);
        const float* rs0 = in + (size_t)e0.x * COUT;
        const float* rs1 = in + (size_t)e1.x * COUT;
        accA = fmaf(w0, __ldg(rs0 + lane), fmaf(w1, __ldg(rs1 + lane), accA));
        if (lane < 8)
            accB = fmaf(w0, __ldg(rs0 + 32 + lane), fmaf(w1, __ldg(rs1 + 32 + lane), accB));
    }
    if (j < end) {
        int2 e0 = __ldg(edge + j);
        float w = __int_as_float(e0.y);
        const float* rs = in + (size_t)e0.x * COUT;
        accA = fmaf(w, __ldg(rs + lane), accA);
        if (lane < 8) accB = fmaf(w, __ldg(rs + 32 + lane), accB);
    }
    float b = (lane < 8) ? accB : -INFINITY;
    float m = fmaxf(accA, b);
#pragma unroll
    for (int o = 16; o > 0; o >>= 1) m = fmaxf(m, __shfl_xor_sync(0xffffffffu, m, o));
    float s = expf(accA - m) + ((lane < 8) ? expf(accB - m) : 0.f);
#pragma unroll
    for (int o = 16; o > 0; o >>= 1) s += __shfl_xor_sync(0xffffffffu, s, o);
    float ls = logf(s);
    float* w = out + (size_t)node * COUT;
    w[lane] = accA - m - ls;
    if (lane < 8) w[32 + lane] = accB - m - ls;
}

// ---------------- host ----------------
static inline int cdiv(int a, int b) { return (a + b - 1) / b; }

extern "C" void kernel_launch(void* const* d_in, const int* in_sizes, int n_in,
                              void* d_out, int out_size) {
    const float* x    = (const float*)d_in[0];
    const int*   ei   = (const int*)d_in[1];
    const float* W1   = (const float*)d_in[2];
    const float* b1   = (const float*)d_in[3];
    const float* a1   = (const float*)d_in[4];
    const float* W2   = (const float*)d_in[5];
    const float* b2   = (const float*)d_in[6];
    const float* a2   = (const float*)d_in[7];
    const float* g2   = (const float*)d_in[8];
    const float* W3   = (const float*)d_in[9];
    const float* b3   = (const float*)d_in[10];
    const float* a3   = (const float*)d_in[11];
    const float* g3   = (const float*)d_in[12];
    const float* bn1g = (const float*)d_in[13];
    const float* bn1b = (const float*)d_in[14];
    const float* bn2g = (const float*)d_in[15];
    const float* bn2b = (const float*)d_in[16];

    const int N = in_sizes[0] / KDIM;
    const int E = in_sizes[1] / 2;
    const int* src = ei;
    const int* dst = ei + E;

    float *buf1, *buf2, *dinv, *Wq1, *Wq2, *Wq3, *stats1, *stats2;
    int *deg, *rowptr, *cursor, *tpref, *bsum;
    int2* edge;
    cudaGetSymbolAddress((void**)&buf1,   g_buf1);
    cudaGetSymbolAddress((void**)&buf2,   g_buf2);
    cudaGetSymbolAddress((void**)&dinv,   g_dinv);
    cudaGetSymbolAddress((void**)&deg,    g_deg);
    cudaGetSymbolAddress((void**)&rowptr, g_rowptr);
    cudaGetSymbolAddress((void**)&cursor, g_cursor);
    cudaGetSymbolAddress((void**)&edge,   g_edge);
    cudaGetSymbolAddress((void**)&Wq1,    g_Wq1);
    cudaGetSymbolAddress((void**)&Wq2,    g_Wq2);
    cudaGetSymbolAddress((void**)&Wq3,    g_Wq3);
    cudaGetSymbolAddress((void**)&stats1, g_stats1);
    cudaGetSymbolAddress((void**)&stats2, g_stats2);
    cudaGetSymbolAddress((void**)&tpref,  g_tpref);
    cudaGetSymbolAddress((void**)&bsum,   g_bsum);

    const int TB = 256;
    const int GB = cdiv(N, TROWS);

    // graph preprocessing + weight quant
    k_init_quant<<<cdiv(N, TB), TB>>>(deg, stats1, stats2, W1, a1, W2, a2, W3, a3,
                                      Wq1, Wq2, Wq3, N);
    k_count_deg<<<cdiv(E, TB), TB>>>(dst, deg, E);
    k_scan_p1<<<SCAN_B, SCAN_T>>>(deg, dinv, tpref, bsum, N);
    k_scan_p2<<<1, SCAN_B>>>(bsum);
    k_scan_p3<<<SCAN_B, SCAN_T>>>(deg, tpref, bsum, rowptr, cursor, N, E);
    k_scatter<<<cdiv(E, TB), TB>>>(src, dst, dinv, cursor, edge, E);

    // ---- layer 1 ----
    k_gemm_tiled<false><<<GB, 256>>>(x, Wq1, b1, buf1, nullptr, nullptr, nullptr, nullptr, N);
    k_agg_csr128_stats<<<AGG_BLOCKS, 256>>>(rowptr, edge, dinv, buf1, buf2, stats1, N);

    // ---- layer 2 (BN finalize + BN+ReLU+fq fused into GEMM) ----
    k_gemm_tiled<true><<<GB, 256>>>(buf2, Wq2, b2, buf1, stats1, bn1g, bn1b, g2, N);
    k_agg_csr128_stats<<<AGG_BLOCKS, 256>>>(rowptr, edge, dinv, buf1, buf2, stats2, N);

    // ---- layer 3 (output, C=40; BN fused into GEMM, log-softmax into agg) ----
    k_gemm40<<<cdiv(N * 32, TB), TB>>>(buf2, Wq3, b3, buf1, stats2, bn2g, bn2b, g3, N);
    k_agg40_lsm<<<cdiv(N * 32, TB), TB>>>(rowptr, edge, dinv, buf1, (float*)d_out, N);
}